// round 12
// baseline (speedup 1.0000x reference)
#include <cuda_runtime.h>
#include <cstdint>

// Problem constants
#define BB   64
#define DD   920
#define NSMP 920
#define KK   32
#define TOT  (BB * NSMP * DD)   // 54,169,600
#define HALF (TOT / 2)          // 27,084,800
#define NCTA ((NSMP / 4) * (BB / 2))   // 7360 CTAs in the fused grid

// Fixed-point accumulator for s[b,k]: sum of round(wa*2^22), <= 920*2^22 < 2^32.
// Zero-initialized at module load; the last-CTA epilogue restores it to zero
// after each consumption, so every launch / graph replay starts from 0.
__device__ unsigned g_s[BB * KK];     // 8 KB
__device__ unsigned g_ticket;         // last-CTA election; re-armed to 0

#define QSCALE 4194304.0f             // 2^22

// ---------------------------------------------------------------------------
// threefry2x32 (JAX-exact), both outputs returned
// ---------------------------------------------------------------------------
__device__ __forceinline__ unsigned rotl32(unsigned x, int r) {
    return __funnelshift_l(x, x, r);
}

__device__ __forceinline__ uint2 threefry(unsigned c0, unsigned c1) {
    const unsigned ks0 = 0u, ks1 = 1u, ks2 = 0x1BD11BDAu ^ 0u ^ 1u;
    unsigned x0 = c0 + ks0;
    unsigned x1 = c1 + ks1;
#define RND(r) { x0 += x1; x1 = rotl32(x1, r); x1 ^= x0; }
    RND(13) RND(15) RND(26) RND(6)   x0 += ks1; x1 += ks2 + 1u;
    RND(17) RND(29) RND(16) RND(24)  x0 += ks2; x1 += ks0 + 2u;
    RND(13) RND(15) RND(26) RND(6)   x0 += ks0; x1 += ks1 + 3u;
    RND(17) RND(29) RND(16) RND(24)  x0 += ks1; x1 += ks2 + 4u;
    RND(13) RND(15) RND(26) RND(6)   x0 += ks2; x1 += ks0 + 5u;
#undef RND
    return make_uint2(x0, x1);
}

// ---------------------------------------------------------------------------
// Packed f32x2 helpers (Blackwell): per-half IEEE rn -> bit-identical to the
// scalar fmaf/fmul chain, at half the fma-pipe instruction count.
// ---------------------------------------------------------------------------
__device__ __forceinline__ unsigned long long pk2(float lo, float hi) {
    unsigned long long r;
    asm("mov.b64 %0, {%1, %2};" : "=l"(r) : "f"(lo), "f"(hi));
    return r;
}
__device__ __forceinline__ void upk2(unsigned long long v, float& lo, float& hi) {
    asm("mov.b64 {%0, %1}, %2;" : "=f"(lo), "=f"(hi) : "l"(v));
}
__device__ __forceinline__ unsigned long long fma2_(unsigned long long a,
                                                    unsigned long long b,
                                                    unsigned long long c) {
    unsigned long long r;
    asm("fma.rn.f32x2 %0, %1, %2, %3;" : "=l"(r) : "l"(a), "l"(b), "l"(c));
    return r;
}
__device__ __forceinline__ unsigned long long mul2_(unsigned long long a,
                                                    unsigned long long b) {
    unsigned long long r;
    asm("mul.rn.f32x2 %0, %1, %2;" : "=l"(r) : "l"(a), "l"(b));
    return r;
}
__device__ __forceinline__ unsigned long long add2_(unsigned long long a,
                                                    unsigned long long b) {
    unsigned long long r;
    asm("add.rn.f32x2 %0, %1, %2;" : "=l"(r) : "l"(a), "l"(b));
    return r;
}

// Rare (w >= 5, ~0.34% per value) tail: identical to the w>=5 branch of the
// original scalar erfinv path -> bit-identical where it is applied.
__device__ __noinline__ float erfinv_tail5(float u, float w) {
    w = sqrtf(w) - 3.0f;
    float p = -0.000200214257f;
    p = fmaf(p, w, 0.000100950558f);
    p = fmaf(p, w, 0.00134934322f);
    p = fmaf(p, w, -0.00367342844f);
    p = fmaf(p, w, 0.00573950773f);
    p = fmaf(p, w, -0.0076224613f);
    p = fmaf(p, w, 0.00943887047f);
    p = fmaf(p, w, 1.00167406f);
    p = fmaf(p, w, 2.83297682f);
    return 1.41421356f * (p * u);
}

// Two normals from one threefry output pair.  Central Giles polynomial is
// evaluated unconditionally in packed f32x2 (per-half rn == scalar fmaf chain);
// rare w>=5 halves are individually overwritten by the tail path.
__device__ __forceinline__ void normals2(unsigned b0, unsigned b1,
                                         float& n0, float& n1) {
    const float LO = -0.99999994f;  // nextafterf(-1,0)
    float f0 = __uint_as_float((b0 >> 9) | 0x3f800000u) - 1.0f;
    float f1 = __uint_as_float((b1 >> 9) | 0x3f800000u) - 1.0f;
    float u0 = fmaxf(LO, f0 * 2.0f + LO);
    float u1 = fmaxf(LO, f1 * 2.0f + LO);
    unsigned long long u  = pk2(u0, u1);
    unsigned long long x2 = mul2_(u, u);
    // 1 - x2 via fma(x2,-1,1): exact same rounding as the FSUB
    unsigned long long om = fma2_(x2, pk2(-1.0f, -1.0f), pk2(1.0f, 1.0f));
    float o0, o1;
    upk2(om, o0, o1);
    float w0 = -__logf(o0);
    float w1 = -__logf(o1);
    unsigned long long w = add2_(pk2(w0, w1), pk2(-2.5f, -2.5f));
    unsigned long long p = pk2(2.81022636e-08f, 2.81022636e-08f);
    p = fma2_(p, w, pk2(3.43273939e-07f, 3.43273939e-07f));
    p = fma2_(p, w, pk2(-3.5233877e-06f, -3.5233877e-06f));
    p = fma2_(p, w, pk2(-4.39150654e-06f, -4.39150654e-06f));
    p = fma2_(p, w, pk2(0.00021858087f, 0.00021858087f));
    p = fma2_(p, w, pk2(-0.00125372503f, -0.00125372503f));
    p = fma2_(p, w, pk2(-0.00417768164f, -0.00417768164f));
    p = fma2_(p, w, pk2(0.246640727f, 0.246640727f));
    p = fma2_(p, w, pk2(1.50140941f, 1.50140941f));
    unsigned long long res = mul2_(mul2_(p, u), pk2(1.41421356f, 1.41421356f));
    upk2(res, n0, n1);
    if (__builtin_expect(w0 >= 5.0f, 0)) n0 = erfinv_tail5(u0, w0);
    if (__builtin_expect(w1 >= 5.0f, 0)) n1 = erfinv_tail5(u1, w1);
}

// ---------------------------------------------------------------------------
// Per-row top-32 pipeline.  Register view: slices 0..20 in v[21]; slices
// 21..28 stay smem-resident (extra[j*32], j=0..7, already sentinel-filled for
// d >= DD).  Staged threshold search, index-ordered ballot compaction,
// exact-32 inner bisection (ballot/popc), rank-by-position, fixed-point
// integer atomic accumulate of wa[d] into s[b, rank].
// ---------------------------------------------------------------------------
__device__ __forceinline__ void process_row(float (&v)[21], const float* extra,
                                            int b, int lane, int warpid,
                                            const float* myrow,
                                            float (*s_val)[64],
                                            unsigned short (*s_idx)[64]) {
    float t = 1.0f;
    int c = 0;
    {
        float tl = 0.85f, th = 1.15f;
        for (int it = 0; it < 8; it++) {
            int lc = 0;
#pragma unroll
            for (int s = 0; s < 21; s++) lc += (v[s] > t) ? 1 : 0;
#pragma unroll
            for (int j = 0; j < 8; j++) lc += (extra[j * 32] > t) ? 1 : 0;
            c = __reduce_add_sync(0xffffffffu, lc);
            if (c >= 32 && c <= 64) break;
            if (c < 32) th = t; else tl = t;
            t = 0.5f * (tl + th);
        }
    }
    if (c < 32 || c > 64) {   // essentially never taken; guarantees the window
        float tl = -8.0f, th = 8.0f;
        t = 0.0f;
        for (int it = 0; it < 60; it++) {
            int lc = 0;
#pragma unroll
            for (int s = 0; s < 21; s++) lc += (v[s] > t) ? 1 : 0;
#pragma unroll
            for (int j = 0; j < 8; j++) lc += (extra[j * 32] > t) ? 1 : 0;
            c = __reduce_add_sync(0xffffffffu, lc);
            if (c >= 32 && c <= 64) break;
            if (c < 32) th = t; else tl = t;
            t = 0.5f * (tl + th);
        }
    }

    // compact candidates (ascending-d order) into (val, idx) slots
    int base = 0;
#pragma unroll
    for (int s = 0; s < 21; s++) {
        bool p = v[s] > t;
        unsigned bal = __ballot_sync(0xffffffffu, p);
        if (p) {
            int pos = base + __popc(bal & ((1u << lane) - 1u));
            if (pos < 64) {
                s_val[warpid][pos] = v[s];
                s_idx[warpid][pos] = (unsigned short)(s * 32 + lane);
            }
        }
        base += __popc(bal);
    }
#pragma unroll
    for (int j = 0; j < 8; j++) {
        float val = extra[j * 32];
        bool p = val > t;
        unsigned bal = __ballot_sync(0xffffffffu, p);
        if (p) {
            int pos = base + __popc(bal & ((1u << lane) - 1u));
            if (pos < 64) {
                s_val[warpid][pos] = val;
                s_idx[warpid][pos] = (unsigned short)((21 + j) * 32 + lane);
            }
        }
        base += __popc(bal);
    }
    __syncwarp();

    float s0 = (lane < c)      ? s_val[warpid][lane]      : -3.0e38f;
    float s1 = (lane + 32 < c) ? s_val[warpid][lane + 32] : -3.0e38f;

    // inner bisection on the <=64 slots: isolate exactly 32
    if (c != 32) {
        float til = t, tih = 1.6f;   // count(>til)=c>=32 ; count(>1.6)=0 always
        for (int it = 0; it < 32; it++) {
            float tm = 0.5f * (til + tih);
            unsigned bb0 = __ballot_sync(0xffffffffu, s0 > tm);
            unsigned bb1 = __ballot_sync(0xffffffffu, s1 > tm);
            int cc = __popc(bb0) + __popc(bb1);
            if (cc >= 32) til = tm; else tih = tm;
            if (cc == 32) break;
        }
        t = til;
    }

    // rank = prefix count of kept slots in position (= ascending-d) order
    bool k0 = s0 > t;
    bool k1 = s1 > t;
    unsigned keep0 = __ballot_sync(0xffffffffu, k0);
    unsigned keep1 = __ballot_sync(0xffffffffu, k1);
    unsigned below = (1u << lane) - 1u;

    if (k0) {
        int r = __popc(keep0 & below);
        if (r < KK) {
            int d = (int)s_idx[warpid][lane];
            unsigned q = __float2uint_rn(myrow[d] * QSCALE);
            atomicAdd(&g_s[b * KK + r], q);
        }
    }
    if (k1) {
        int r = __popc(keep0) + __popc(keep1 & below);
        if (r < KK) {
            int d = (int)s_idx[warpid][lane + 32];
            unsigned q = __float2uint_rn(myrow[d] * QSCALE);
            atomicAdd(&g_s[b * KK + r], q);
        }
    }
}

// ---------------------------------------------------------------------------
// Fused kernel.  CTA = 4 row-pairs (b,n)/(b+32,n), 8 warps.  The threefry
// pairing (j, j+HALF) couples rows b and b+32 at equal (n,d): warps 0-3
// generate slices 0..14 for pair wp (keep row-A in regs, export row-B via
// ex_B), warps 4-7 generate slices 15..28 (keep row-B s15..20 in regs,
// export row-A via ex_A, self-stash row-B s21..28 into ex_B2).  After one
// sync each warp holds register slices 0..20 plus an 8-slice smem tail
// (s21..28) -> only 21 v-registers live, enabling 6 CTAs/SM.
// The LAST CTA (global ticket) consumes g_s, emits the bboxes, and re-zeros
// the accumulator + ticket for the next launch / graph replay.
// ---------------------------------------------------------------------------
__global__ void __launch_bounds__(256, 6) ftopk_kernel(const float* __restrict__ wa,
                                                       float* __restrict__ out) {
    __shared__ float s_waA[DD];
    __shared__ float s_waB[DD];
    __shared__ float ex_B[4][15][32];   // A-warps -> B-warps: row-B, s0..14
    __shared__ float ex_A[4][14][32];   // B-warps -> A-warps: row-A, s15..28
    __shared__ float ex_B2[4][8][32];   // B-warps self: row-B, s21..28
    __shared__ float s_val[8][64];
    __shared__ unsigned short s_idx[8][64];
    __shared__ bool s_last;

    int b = blockIdx.y;                 // 0..31 (pair: b and b+32)
    int warpid = threadIdx.x >> 5;
    int lane = threadIdx.x & 31;
    int wp = warpid & 3;
    bool isB = warpid >= 4;

    for (int i = threadIdx.x; i < DD; i += 256) {
        s_waA[i] = wa[b * DD + i];
        s_waB[i] = wa[(b + 32) * DD + i];
    }
    __syncthreads();

    int n = blockIdx.x * 4 + wp;        // gridDim.x = 230 -> n in [0,920)
    unsigned rowbase = (unsigned)((b * NSMP + n) * DD);  // < HALF (b < 32)

    float v[21];
    if (!isB) {
#pragma unroll
        for (int s = 0; s < 15; s++) {
            int d = s * 32 + lane;
            unsigned i = rowbase + (unsigned)d;
            uint2 r = threefry(i, i + (unsigned)HALF);
            float n0, n1;
            normals2(r.x, r.y, n0, n1);
            v[s] = s_waA[d] + 0.1f * n0;
            ex_B[wp][s][lane] = s_waB[d] + 0.1f * n1;
        }
    } else {
#pragma unroll
        for (int s = 15; s < 29; s++) {
            int d = s * 32 + lane;
            float a_val = -3.0e38f, b_val = -3.0e38f;
            if (d < DD) {
                unsigned i = rowbase + (unsigned)d;
                uint2 r = threefry(i, i + (unsigned)HALF);
                float n0, n1;
                normals2(r.x, r.y, n0, n1);
                a_val = s_waA[d] + 0.1f * n0;
                b_val = s_waB[d] + 0.1f * n1;
            }
            ex_A[wp][s - 15][lane] = a_val;
            if (s < 21) v[s] = b_val;
            else        ex_B2[wp][s - 21][lane] = b_val;
        }
    }
    __syncthreads();

    if (!isB) {
#pragma unroll
        for (int s = 15; s < 21; s++) v[s] = ex_A[wp][s - 15][lane];
    } else {
#pragma unroll
        for (int s = 0; s < 15; s++) v[s] = ex_B[wp][s][lane];
    }
    const float* extra = isB ? &ex_B2[wp][0][lane] : &ex_A[wp][6][lane];

    process_row(v, extra, isB ? b + 32 : b, lane, warpid,
                isB ? s_waB : s_waA, s_val, s_idx);

    // ---- last-CTA epilogue: fold g_s -> bboxes, re-arm scratch ----
    __threadfence();                    // each thread: its REDGs visible @gpu
    __syncthreads();
    if (threadIdx.x == 0) {
        unsigned tk = atomicAdd(&g_ticket, 1u);
        s_last = (tk == NCTA - 1u);
    }
    __syncthreads();
    if (s_last) {
        __threadfence();                // acquire side
        for (int idx = threadIdx.x; idx < BB * KK; idx += 256) {
            unsigned acc = atomicExch(&g_s[idx], 0u);   // read + re-zero
            float sv = __uint2float_rn(acc) * (1.0f / (QSCALE * 920.0f));
            float r  = floorf(sv / 40.0f);
            float cc = sv - 40.0f * r;                  // jnp.mod(sv, 40)
            float x0 = (cc < 1.0f ? cc : cc - 1.0f) * 32.0f;
            float y0 = (r  < 1.0f ? r  : r  - 1.0f) * 32.0f;
            float x1 = (cc < 1.0f ? cc + 2.0f : cc + 1.0f) * 32.0f;
            float y1 = (r + 2.0f) * 32.0f;
            ((float4*)out)[idx] = make_float4(x0, y0, x1, y1);
        }
        if (threadIdx.x == 0) g_ticket = 0u;            // re-arm for next launch
    }
}

// ---------------------------------------------------------------------------
extern "C" void kernel_launch(void* const* d_in, const int* in_sizes, int n_in,
                              void* d_out, int out_size) {
    const float* wa = (const float*)d_in[2];   // weight_attn (64,23,40) -> (64,920)
    float* out = (float*)d_out;                // (64,32,4) float32

    ftopk_kernel<<<dim3(NSMP / 4, BB / 2), 256>>>(wa, out);
}

// round 13
// speedup vs baseline: 1.1569x; 1.1569x over previous
#include <cuda_runtime.h>
#include <cstdint>

// Problem constants
#define BB   64
#define DD   920
#define NSMP 920
#define KK   32
#define TOT  (BB * NSMP * DD)   // 54,169,600
#define HALF (TOT / 2)          // 27,084,800
#define NCTA ((NSMP / 4) * (BB / 2))   // 7360 CTAs in the fused grid
#define RCAP 96                  // per-region candidate capacity

// Fixed-point accumulator for s[b,k]: sum of round(wa*2^22), <= 920*2^22 < 2^32.
// Zero-initialized at module load; the last-CTA epilogue restores it to zero
// after each consumption, so every launch / graph replay starts from 0.
__device__ unsigned g_s[BB * KK];     // 8 KB
__device__ unsigned g_ticket;         // last-CTA election; re-armed to 0
__device__ float    g_t0[BB];         // per-batch candidate threshold (prep)

#define QSCALE 4194304.0f             // 2^22

// ---------------------------------------------------------------------------
// threefry2x32 (JAX-exact), both outputs returned
// ---------------------------------------------------------------------------
__device__ __forceinline__ unsigned rotl32(unsigned x, int r) {
    return __funnelshift_l(x, x, r);
}

__device__ __forceinline__ uint2 threefry(unsigned c0, unsigned c1) {
    const unsigned ks0 = 0u, ks1 = 1u, ks2 = 0x1BD11BDAu ^ 0u ^ 1u;
    unsigned x0 = c0 + ks0;
    unsigned x1 = c1 + ks1;
#define RND(r) { x0 += x1; x1 = rotl32(x1, r); x1 ^= x0; }
    RND(13) RND(15) RND(26) RND(6)   x0 += ks1; x1 += ks2 + 1u;
    RND(17) RND(29) RND(16) RND(24)  x0 += ks2; x1 += ks0 + 2u;
    RND(13) RND(15) RND(26) RND(6)   x0 += ks0; x1 += ks1 + 3u;
    RND(17) RND(29) RND(16) RND(24)  x0 += ks1; x1 += ks2 + 4u;
    RND(13) RND(15) RND(26) RND(6)   x0 += ks2; x1 += ks0 + 5u;
#undef RND
    return make_uint2(x0, x1);
}

// bits -> u in [-1, 1): identical expression to all prior passing rounds.
__device__ __forceinline__ float bits_to_u(unsigned b) {
    const float LO = -0.99999994f;  // nextafterf(-1,0)
    float f = __uint_as_float((b >> 9) | 0x3f800000u) - 1.0f;
    return fmaxf(LO, f * 2.0f + LO);
}

// Rare (w >= 5, ~0.34% per value) tail: identical to prior rounds.
__device__ __noinline__ float erfinv_tail5(float u, float w) {
    w = sqrtf(w) - 3.0f;
    float p = -0.000200214257f;
    p = fmaf(p, w, 0.000100950558f);
    p = fmaf(p, w, 0.00134934322f);
    p = fmaf(p, w, -0.00367342844f);
    p = fmaf(p, w, 0.00573950773f);
    p = fmaf(p, w, -0.0076224613f);
    p = fmaf(p, w, 0.00943887047f);
    p = fmaf(p, w, 1.00167406f);
    p = fmaf(p, w, 2.83297682f);
    return 1.41421356f * (p * u);
}

// u -> sqrt(2)*erfinv(u), bit-identical to prior rounds' per-value math
// (om via fma(x2,-1,1); central Giles Horner; tail for w>=5).
__device__ __forceinline__ float nrm(float u) {
    float x2 = u * u;
    float om = fmaf(x2, -1.0f, 1.0f);
    float w = -__logf(om);
    if (__builtin_expect(w < 5.0f, 1)) {
        w -= 2.5f;
        float p = 2.81022636e-08f;
        p = fmaf(p, w, 3.43273939e-07f);
        p = fmaf(p, w, -3.5233877e-06f);
        p = fmaf(p, w, -4.39150654e-06f);
        p = fmaf(p, w, 0.00021858087f);
        p = fmaf(p, w, -0.00125372503f);
        p = fmaf(p, w, -0.00417768164f);
        p = fmaf(p, w, 0.246640727f);
        p = fmaf(p, w, 1.50140941f);
        return (p * u) * 1.41421356f;
    }
    return erfinv_tail5(u, w);
}

// ---------------------------------------------------------------------------
// Prep: per-b threshold t0 with count(wa > t0) ~ 48-49.
// 64 warps across 2 CTAs.  Any t0 is CORRECT (fallback covers); this targets
// the candidate-count sweet spot.
// ---------------------------------------------------------------------------
__global__ void __launch_bounds__(1024) prep_kernel(const float* __restrict__ wa) {
    int gw = blockIdx.x * 32 + (threadIdx.x >> 5);
    int lane = threadIdx.x & 31;
    if (gw >= BB) return;
    const float* row = wa + gw * DD;
    float v[29];
#pragma unroll
    for (int s = 0; s < 29; s++) {
        int d = s * 32 + lane;
        v[s] = (d < DD) ? row[d] : -1e30f;
    }
    float tl = 0.80f, th = 1.05f;
    for (int it = 0; it < 22; it++) {
        float t = 0.5f * (tl + th);
        int lc = 0;
#pragma unroll
        for (int s = 0; s < 29; s++) lc += (v[s] > t) ? 1 : 0;
        int c = __reduce_add_sync(0xffffffffu, lc);
        if (c > 48) tl = t; else th = t;
    }
    if (lane == 0) g_t0[gw] = tl;   // count(wa > tl) >= 49
}

// ---------------------------------------------------------------------------
// Fallback: full bit-identical row pipeline (regen all 29 slices, staged
// search, compaction, exact-32 bisection, rank, emit).  Taken when c0 < 32
// or a candidate region overflows (~1% of rows).  Scratch = the row's own
// candidate arrays (>= 64 floats + 64 u16).
// ---------------------------------------------------------------------------
__device__ __noinline__ void fallback_row(int b_eff, unsigned rowbase, int lane,
                                          bool useHi, const float* myrow,
                                          float* s_val, unsigned short* s_idx) {
    float v[29];
#pragma unroll
    for (int s = 0; s < 29; s++) {
        int d = s * 32 + lane;
        if (d < DD) {
            unsigned i = rowbase + (unsigned)d;
            uint2 r = threefry(i, i + (unsigned)HALF);
            float u = bits_to_u(useHi ? r.y : r.x);
            v[s] = myrow[d] + 0.1f * nrm(u);
        } else v[s] = -3.0e38f;
    }

    float t = 1.0f;
    int c = 0;
    {
        float tl = 0.85f, th = 1.15f;
        for (int it = 0; it < 8; it++) {
            int lc = 0;
#pragma unroll
            for (int s = 0; s < 29; s++) lc += (v[s] > t) ? 1 : 0;
            c = __reduce_add_sync(0xffffffffu, lc);
            if (c >= 32 && c <= 64) break;
            if (c < 32) th = t; else tl = t;
            t = 0.5f * (tl + th);
        }
    }
    if (c < 32 || c > 64) {
        float tl = -8.0f, th = 8.0f;
        t = 0.0f;
        for (int it = 0; it < 60; it++) {
            int lc = 0;
#pragma unroll
            for (int s = 0; s < 29; s++) lc += (v[s] > t) ? 1 : 0;
            c = __reduce_add_sync(0xffffffffu, lc);
            if (c >= 32 && c <= 64) break;
            if (c < 32) th = t; else tl = t;
            t = 0.5f * (tl + th);
        }
    }

    int base = 0;
    unsigned below = (1u << lane) - 1u;
#pragma unroll
    for (int s = 0; s < 29; s++) {
        bool p = v[s] > t;
        unsigned bal = __ballot_sync(0xffffffffu, p);
        if (p) {
            int pos = base + __popc(bal & below);
            if (pos < 64) {
                s_val[pos] = v[s];
                s_idx[pos] = (unsigned short)(s * 32 + lane);
            }
        }
        base += __popc(bal);
    }
    __syncwarp();

    float s0 = (lane < c)      ? s_val[lane]      : -3.0e38f;
    float s1 = (lane + 32 < c) ? s_val[lane + 32] : -3.0e38f;

    if (c != 32) {
        float til = t, tih = 1.6f;
        for (int it = 0; it < 32; it++) {
            float tm = 0.5f * (til + tih);
            unsigned b0 = __ballot_sync(0xffffffffu, s0 > tm);
            unsigned b1 = __ballot_sync(0xffffffffu, s1 > tm);
            int cc = __popc(b0) + __popc(b1);
            if (cc >= 32) til = tm; else tih = tm;
            if (cc == 32) break;
        }
        t = til;
    }

    bool k0 = s0 > t, k1 = s1 > t;
    unsigned keep0 = __ballot_sync(0xffffffffu, k0);
    unsigned keep1 = __ballot_sync(0xffffffffu, k1);
    if (k0) {
        int r = __popc(keep0 & below);
        if (r < KK) {
            int d = (int)s_idx[lane];
            atomicAdd(&g_s[b_eff * KK + r], __float2uint_rn(myrow[d] * QSCALE));
        }
    }
    if (k1) {
        int r = __popc(keep0) + __popc(keep1 & below);
        if (r < KK) {
            int d = (int)s_idx[lane + 32];
            atomicAdd(&g_s[b_eff * KK + r], __float2uint_rn(myrow[d] * QSCALE));
        }
    }
}

// ---------------------------------------------------------------------------
// Fused kernel with candidate pre-filtering.
// Phase 1 (producers): warps 0-3 do slices 0..14, warps 4-7 slices 15..28,
// for BOTH rows of their pair (the threefry (j, j+HALF) pairing couples rows
// b and b+32 at equal (n,d)).  Per value: compute u only, apply the cheap
// conservative bound test  [ u>0.9  OR  wa + 0.183*max(u,0) > t0-eps ]
// (sqrt2*erfinv(u) <= 1.8276*u on [0,0.9] by convexity; <=0 for u<=0), and
// ballot-compact passing (u,d) into per-row regions in ascending-d order.
// Phase 2 (consumers): warp w owns row A, warp w+4 row B.  Dense erfinv on
// the ~125 candidates only, c0 = count(v > t0) (>=32 or fallback), exact-32
// bisection over <=192 slots (6 regs), rank by position, fixed-point emit.
// Last CTA folds g_s -> bboxes and re-arms scratch.
// ---------------------------------------------------------------------------
__global__ void __launch_bounds__(256) ftopk_kernel(const float* __restrict__ wa,
                                                    float* __restrict__ out) {
    __shared__ float s_waA[DD];
    __shared__ float s_waB[DD];
    __shared__ float s_u[4][2][2 * RCAP];            // [pair][row][slot]
    __shared__ unsigned short s_dn[4][2][2 * RCAP];
    __shared__ int s_cnt[4][2][2];                   // [pair][row][lo/hi]
    __shared__ bool s_last;

    int b = blockIdx.y;                 // 0..31 (pair: b and b+32)
    int warpid = threadIdx.x >> 5;
    int lane = threadIdx.x & 31;
    int wp = warpid & 3;
    bool isB = warpid >= 4;
    unsigned below = (1u << lane) - 1u;

    for (int i = threadIdx.x; i < DD; i += 256) {
        s_waA[i] = wa[b * DD + i];
        s_waB[i] = wa[(b + 32) * DD + i];
    }
    float t0A = g_t0[b];
    float t0B = g_t0[b + 32];
    float CA = t0A - 1e-5f;
    float CB = t0B - 1e-5f;
    __syncthreads();

    int n = blockIdx.x * 4 + wp;        // gridDim.x = 230 -> n in [0,920)
    unsigned rowbase = (unsigned)((b * NSMP + n) * DD);  // < HALF (b < 32)

    // ---- phase 1: generate u, test, compact candidates ----
    {
        int sBeg = isB ? 15 : 0;
        int sEnd = isB ? 29 : 15;
        int off  = isB ? RCAP : 0;
        int baseA = 0, baseB = 0;
        float* uA = s_u[wp][0]; unsigned short* dA = s_dn[wp][0];
        float* uB = s_u[wp][1]; unsigned short* dB = s_dn[wp][1];
        for (int s = sBeg; s < sEnd; s++) {
            int d = s * 32 + lane;
            bool ok = d < DD;
            int dd = ok ? d : (DD - 1);
            unsigned i = rowbase + (unsigned)d;
            uint2 r = threefry(i, i + (unsigned)HALF);
            float u0 = bits_to_u(r.x);
            float u1 = bits_to_u(r.y);
            float a0 = s_waA[dd];
            float a1 = s_waB[dd];
            bool cA = ok && ((u0 > 0.9f) || (fmaf(0.183f, fmaxf(u0, 0.0f), a0) > CA));
            bool cB = ok && ((u1 > 0.9f) || (fmaf(0.183f, fmaxf(u1, 0.0f), a1) > CB));
            unsigned balA = __ballot_sync(0xffffffffu, cA);
            if (cA) {
                int pos = baseA + __popc(balA & below);
                if (pos < RCAP) { uA[off + pos] = u0; dA[off + pos] = (unsigned short)d; }
            }
            baseA += __popc(balA);
            unsigned balB = __ballot_sync(0xffffffffu, cB);
            if (cB) {
                int pos = baseB + __popc(balB & below);
                if (pos < RCAP) { uB[off + pos] = u1; dB[off + pos] = (unsigned short)d; }
            }
            baseB += __popc(balB);
        }
        if (lane == 0) {
            s_cnt[wp][0][isB ? 1 : 0] = baseA;
            s_cnt[wp][1][isB ? 1 : 0] = baseB;
        }
    }
    __syncthreads();

    // ---- phase 2: consumer (one row per warp) ----
    {
        int r = isB ? 1 : 0;
        int b_eff = isB ? (b + 32) : b;
        float t0 = isB ? t0B : t0A;
        const float* myrow = isB ? s_waB : s_waA;
        float* uR = s_u[wp][r];
        unsigned short* dR = s_dn[wp][r];
        int n_lo = s_cnt[wp][r][0];
        int n_hi = s_cnt[wp][r][1];
        bool fb = (n_lo > RCAP) || (n_hi > RCAP);

        float sv[6];
#pragma unroll
        for (int k = 0; k < 6; k++) sv[k] = -3.0e38f;

        if (!fb) {
            int ntot = n_lo + n_hi;
            int kmax = (ntot + 31) >> 5;
#pragma unroll
            for (int k = 0; k < 6; k++) {
                if (k < kmax) {
                    int i = (k << 5) + lane;
                    if (i < ntot) {
                        int ph = (i < n_lo) ? i : (RCAP + i - n_lo);
                        float u = uR[ph];
                        int d = (int)dR[ph];
                        sv[k] = myrow[d] + 0.1f * nrm(u);
                    }
                }
            }
            int c0 = 0;
#pragma unroll
            for (int k = 0; k < 6; k++)
                c0 += __popc(__ballot_sync(0xffffffffu, sv[k] > t0));
            if (c0 < 32) fb = true;

            if (!fb) {
                float t = t0;
                if (c0 != 32) {
                    float til = t0, tih = 1.6f;
                    for (int it = 0; it < 32; it++) {
                        float tm = 0.5f * (til + tih);
                        int cc = 0;
#pragma unroll
                        for (int k = 0; k < 6; k++)
                            cc += __popc(__ballot_sync(0xffffffffu, sv[k] > tm));
                        if (cc >= 32) til = tm; else tih = tm;
                        if (cc == 32) break;
                    }
                    t = til;
                }
                unsigned bal[6];
#pragma unroll
                for (int k = 0; k < 6; k++)
                    bal[k] = __ballot_sync(0xffffffffu, sv[k] > t);
                int pre = 0;
#pragma unroll
                for (int k = 0; k < 6; k++) {
                    if (sv[k] > t) {
                        int rk = pre + __popc(bal[k] & below);
                        if (rk < KK) {
                            int i = (k << 5) + lane;
                            int ph = (i < n_lo) ? i : (RCAP + i - n_lo);
                            int d = (int)dR[ph];
                            atomicAdd(&g_s[b_eff * KK + rk],
                                      __float2uint_rn(myrow[d] * QSCALE));
                        }
                    }
                    pre += __popc(bal[k]);
                }
            }
        }
        if (fb) {
            fallback_row(b_eff, rowbase, lane, isB, myrow, uR, dR);
        }
    }

    // ---- last-CTA epilogue: fold g_s -> bboxes, re-arm scratch ----
    __threadfence();
    __syncthreads();
    if (threadIdx.x == 0) {
        unsigned tk = atomicAdd(&g_ticket, 1u);
        s_last = (tk == NCTA - 1u);
    }
    __syncthreads();
    if (s_last) {
        __threadfence();
        for (int idx = threadIdx.x; idx < BB * KK; idx += 256) {
            unsigned acc = atomicExch(&g_s[idx], 0u);   // read + re-zero
            float sv = __uint2float_rn(acc) * (1.0f / (QSCALE * 920.0f));
            float r  = floorf(sv / 40.0f);
            float cc = sv - 40.0f * r;                  // jnp.mod(sv, 40)
            float x0 = (cc < 1.0f ? cc : cc - 1.0f) * 32.0f;
            float y0 = (r  < 1.0f ? r  : r  - 1.0f) * 32.0f;
            float x1 = (cc < 1.0f ? cc + 2.0f : cc + 1.0f) * 32.0f;
            float y1 = (r + 2.0f) * 32.0f;
            ((float4*)out)[idx] = make_float4(x0, y0, x1, y1);
        }
        if (threadIdx.x == 0) g_ticket = 0u;
    }
}

// ---------------------------------------------------------------------------
extern "C" void kernel_launch(void* const* d_in, const int* in_sizes, int n_in,
                              void* d_out, int out_size) {
    const float* wa = (const float*)d_in[2];   // weight_attn (64,23,40) -> (64,920)
    float* out = (float*)d_out;                // (64,32,4) float32

    prep_kernel<<<2, 1024>>>(wa);
    ftopk_kernel<<<dim3(NSMP / 4, BB / 2), 256>>>(wa, out);
}

// round 14
// speedup vs baseline: 1.2296x; 1.0629x over previous
#include <cuda_runtime.h>
#include <cstdint>

// Problem constants
#define BB   64
#define DD   920
#define NSMP 920
#define KK   32
#define TOT  (BB * NSMP * DD)   // 54,169,600
#define HALF (TOT / 2)          // 27,084,800
#define NCTA ((NSMP / 4) * (BB / 2))   // 7360 CTAs in the fused grid
#define RCAP 96                  // per-region candidate capacity

// Fixed-point accumulator for s[b,k]: sum of round(wa*2^22), <= 920*2^22 < 2^32.
// Zero-initialized at module load; the last-CTA epilogue restores it to zero
// after each consumption, so every launch / graph replay starts from 0.
__device__ unsigned g_s[BB * KK];     // 8 KB
__device__ unsigned g_ticket;         // last-CTA election; re-armed to 0
__device__ float    g_t0[BB];         // per-batch candidate threshold (prep)

#define QSCALE 4194304.0f             // 2^22

// ---------------------------------------------------------------------------
// threefry2x32 (JAX-exact), both outputs returned
// ---------------------------------------------------------------------------
__device__ __forceinline__ unsigned rotl32(unsigned x, int r) {
    return __funnelshift_l(x, x, r);
}

__device__ __forceinline__ uint2 threefry(unsigned c0, unsigned c1) {
    const unsigned ks0 = 0u, ks1 = 1u, ks2 = 0x1BD11BDAu ^ 0u ^ 1u;
    unsigned x0 = c0 + ks0;
    unsigned x1 = c1 + ks1;
#define RND(r) { x0 += x1; x1 = rotl32(x1, r); x1 ^= x0; }
    RND(13) RND(15) RND(26) RND(6)   x0 += ks1; x1 += ks2 + 1u;
    RND(17) RND(29) RND(16) RND(24)  x0 += ks2; x1 += ks0 + 2u;
    RND(13) RND(15) RND(26) RND(6)   x0 += ks0; x1 += ks1 + 3u;
    RND(17) RND(29) RND(16) RND(24)  x0 += ks1; x1 += ks2 + 4u;
    RND(13) RND(15) RND(26) RND(6)   x0 += ks2; x1 += ks0 + 5u;
#undef RND
    return make_uint2(x0, x1);
}

// bits -> u in [-1, 1): identical expression to all prior passing rounds.
__device__ __forceinline__ float bits_to_u(unsigned b) {
    const float LO = -0.99999994f;  // nextafterf(-1,0)
    float f = __uint_as_float((b >> 9) | 0x3f800000u) - 1.0f;
    return fmaxf(LO, f * 2.0f + LO);
}

// Rare (w >= 5, ~0.34% per value) tail: identical to prior rounds.
__device__ __noinline__ float erfinv_tail5(float u, float w) {
    w = sqrtf(w) - 3.0f;
    float p = -0.000200214257f;
    p = fmaf(p, w, 0.000100950558f);
    p = fmaf(p, w, 0.00134934322f);
    p = fmaf(p, w, -0.00367342844f);
    p = fmaf(p, w, 0.00573950773f);
    p = fmaf(p, w, -0.0076224613f);
    p = fmaf(p, w, 0.00943887047f);
    p = fmaf(p, w, 1.00167406f);
    p = fmaf(p, w, 2.83297682f);
    return 1.41421356f * (p * u);
}

// u -> sqrt(2)*erfinv(u), bit-identical to prior rounds' per-value math.
__device__ __forceinline__ float nrm(float u) {
    float x2 = u * u;
    float om = fmaf(x2, -1.0f, 1.0f);
    float w = -__logf(om);
    if (__builtin_expect(w < 5.0f, 1)) {
        w -= 2.5f;
        float p = 2.81022636e-08f;
        p = fmaf(p, w, 3.43273939e-07f);
        p = fmaf(p, w, -3.5233877e-06f);
        p = fmaf(p, w, -4.39150654e-06f);
        p = fmaf(p, w, 0.00021858087f);
        p = fmaf(p, w, -0.00125372503f);
        p = fmaf(p, w, -0.00417768164f);
        p = fmaf(p, w, 0.246640727f);
        p = fmaf(p, w, 1.50140941f);
        return (p * u) * 1.41421356f;
    }
    return erfinv_tail5(u, w);
}

// Bits-domain conservative filter threshold for one d:
//   pass  <=>  bits >= B.   B chosen so that pruned values provably satisfy
//   wa + 0.1*nrm(u) <= t0:  u <= ub <= 0.9 with sqrt2*erfinv(u) <= 1.83*u on
//   [0,0.9] (convexity), ub = min(0.9, (C-wa)/0.183 - eps); wa >= C -> always
//   pass (B=0).  The u->bits inversion uses a 2-unit floor slack to absorb
//   every rounding step in bits_to_u.
__device__ __forceinline__ unsigned mkB(float wav, float C) {
    float cw = C - wav;
    if (cw <= 0.0f) return 0u;                       // always pass
    float ub = fminf(0.9f, fmaf(cw, 5.46448f, -1e-4f));
    int M = (int)floorf((ub + 1.0f) * 4194304.0f) - 2;
    if (M < 0) return 0u;                            // always pass
    return ((unsigned)(M + 1)) << 9;
}

// ---------------------------------------------------------------------------
// Prep: per-b threshold t0 with count(wa > t0) ~ 48-49.
// ---------------------------------------------------------------------------
__global__ void __launch_bounds__(1024) prep_kernel(const float* __restrict__ wa) {
    int gw = blockIdx.x * 32 + (threadIdx.x >> 5);
    int lane = threadIdx.x & 31;
    if (gw >= BB) return;
    const float* row = wa + gw * DD;
    float v[29];
#pragma unroll
    for (int s = 0; s < 29; s++) {
        int d = s * 32 + lane;
        v[s] = (d < DD) ? row[d] : -1e30f;
    }
    float tl = 0.80f, th = 1.05f;
    for (int it = 0; it < 22; it++) {
        float t = 0.5f * (tl + th);
        int lc = 0;
#pragma unroll
        for (int s = 0; s < 29; s++) lc += (v[s] > t) ? 1 : 0;
        int c = __reduce_add_sync(0xffffffffu, lc);
        if (c > 48) tl = t; else th = t;
    }
    if (lane == 0) g_t0[gw] = tl;   // count(wa > tl) >= 49
}

// ---------------------------------------------------------------------------
// Fallback: full bit-identical row pipeline.  Taken when c0 < 32 or a
// candidate region overflows (rare).  Scratch = the row's candidate slots.
// ---------------------------------------------------------------------------
__device__ __noinline__ void fallback_row(int b_eff, unsigned rowbase, int lane,
                                          bool useHi, const float* myrow,
                                          float* s_val, unsigned short* s_idx) {
    float v[29];
#pragma unroll
    for (int s = 0; s < 29; s++) {
        int d = s * 32 + lane;
        if (d < DD) {
            unsigned i = rowbase + (unsigned)d;
            uint2 r = threefry(i, i + (unsigned)HALF);
            float u = bits_to_u(useHi ? r.y : r.x);
            v[s] = myrow[d] + 0.1f * nrm(u);
        } else v[s] = -3.0e38f;
    }

    float t = 1.0f;
    int c = 0;
    {
        float tl = 0.85f, th = 1.15f;
        for (int it = 0; it < 8; it++) {
            int lc = 0;
#pragma unroll
            for (int s = 0; s < 29; s++) lc += (v[s] > t) ? 1 : 0;
            c = __reduce_add_sync(0xffffffffu, lc);
            if (c >= 32 && c <= 64) break;
            if (c < 32) th = t; else tl = t;
            t = 0.5f * (tl + th);
        }
    }
    if (c < 32 || c > 64) {
        float tl = -8.0f, th = 8.0f;
        t = 0.0f;
        for (int it = 0; it < 60; it++) {
            int lc = 0;
#pragma unroll
            for (int s = 0; s < 29; s++) lc += (v[s] > t) ? 1 : 0;
            c = __reduce_add_sync(0xffffffffu, lc);
            if (c >= 32 && c <= 64) break;
            if (c < 32) th = t; else tl = t;
            t = 0.5f * (tl + th);
        }
    }

    int base = 0;
    unsigned below = (1u << lane) - 1u;
#pragma unroll
    for (int s = 0; s < 29; s++) {
        bool p = v[s] > t;
        unsigned bal = __ballot_sync(0xffffffffu, p);
        if (p) {
            int pos = base + __popc(bal & below);
            if (pos < 64) {
                s_val[pos] = v[s];
                s_idx[pos] = (unsigned short)(s * 32 + lane);
            }
        }
        base += __popc(bal);
    }
    __syncwarp();

    float s0 = (lane < c)      ? s_val[lane]      : -3.0e38f;
    float s1 = (lane + 32 < c) ? s_val[lane + 32] : -3.0e38f;

    if (c != 32) {
        float til = t, tih = 1.6f;
        for (int it = 0; it < 32; it++) {
            float tm = 0.5f * (til + tih);
            unsigned b0 = __ballot_sync(0xffffffffu, s0 > tm);
            unsigned b1 = __ballot_sync(0xffffffffu, s1 > tm);
            int cc = __popc(b0) + __popc(b1);
            if (cc >= 32) til = tm; else tih = tm;
            if (cc == 32) break;
        }
        t = til;
    }

    bool k0 = s0 > t, k1 = s1 > t;
    unsigned keep0 = __ballot_sync(0xffffffffu, k0);
    unsigned keep1 = __ballot_sync(0xffffffffu, k1);
    if (k0) {
        int r = __popc(keep0 & below);
        if (r < KK) {
            int d = (int)s_idx[lane];
            atomicAdd(&g_s[b_eff * KK + r], __float2uint_rn(myrow[d] * QSCALE));
        }
    }
    if (k1) {
        int r = __popc(keep0) + __popc(keep1 & below);
        if (r < KK) {
            int d = (int)s_idx[lane + 32];
            atomicAdd(&g_s[b_eff * KK + r], __float2uint_rn(myrow[d] * QSCALE));
        }
    }
}

// ---------------------------------------------------------------------------
// Fused kernel with bits-domain candidate pre-filtering.
// Phase 1: per value, ONE unsigned compare (bits >= B[d]) decides candidacy;
// passers store packed (d, bits) via STS.64 in ascending-d order.
// Phase 2: one row per warp; reconstruct u from bits (identical expression),
// dense erfinv on ~125 candidates, exact-32 bisection, rank, emit.
// Last CTA folds g_s -> bboxes and re-arms scratch.
// ---------------------------------------------------------------------------
__global__ void __launch_bounds__(256) ftopk_kernel(const float* __restrict__ wa,
                                                    float* __restrict__ out) {
    __shared__ float s_waA[DD];
    __shared__ float s_waB[DD];
    __shared__ unsigned s_BA[DD];                    // bits thresholds, row A
    __shared__ unsigned s_BB[DD];                    // bits thresholds, row B
    __shared__ uint2 s_cand[4][2][2 * RCAP];         // [pair][row][slot] (d, bits)
    __shared__ int s_cnt[4][2][2];                   // [pair][row][lo/hi]
    __shared__ bool s_last;

    int b = blockIdx.y;                 // 0..31 (pair: b and b+32)
    int warpid = threadIdx.x >> 5;
    int lane = threadIdx.x & 31;
    int wp = warpid & 3;
    bool isB = warpid >= 4;
    unsigned below = (1u << lane) - 1u;

    float t0A = g_t0[b];
    float t0B = g_t0[b + 32];
    float CA = t0A - 1e-5f;
    float CB = t0B - 1e-5f;
    for (int i = threadIdx.x; i < DD; i += 256) {
        float a0 = wa[b * DD + i];
        float a1 = wa[(b + 32) * DD + i];
        s_waA[i] = a0;  s_BA[i] = mkB(a0, CA);
        s_waB[i] = a1;  s_BB[i] = mkB(a1, CB);
    }
    __syncthreads();

    int n = blockIdx.x * 4 + wp;        // gridDim.x = 230 -> n in [0,920)
    unsigned rowbase = (unsigned)((b * NSMP + n) * DD);  // < HALF (b < 32)

    // ---- phase 1: threefry + single-compare filter + compact (d,bits) ----
    {
        int sBeg = isB ? 15 : 0;
        int sEnd = isB ? 29 : 15;
        int off  = isB ? RCAP : 0;
        int baseA = 0, baseB = 0;
        uint2* candA = s_cand[wp][0];
        uint2* candB = s_cand[wp][1];
        for (int s = sBeg; s < sEnd; s++) {
            int d = s * 32 + lane;
            bool ok = d < DD;
            int dd = ok ? d : (DD - 1);
            unsigned i = rowbase + (unsigned)d;
            uint2 r = threefry(i, i + (unsigned)HALF);
            bool cA = ok && (r.x >= s_BA[dd]);
            bool cB = ok && (r.y >= s_BB[dd]);
            unsigned balA = __ballot_sync(0xffffffffu, cA);
            if (cA) {
                int pos = baseA + __popc(balA & below);
                if (pos < RCAP)
                    candA[off + pos] = make_uint2((unsigned)d, r.x);
            }
            baseA += __popc(balA);
            unsigned balB = __ballot_sync(0xffffffffu, cB);
            if (cB) {
                int pos = baseB + __popc(balB & below);
                if (pos < RCAP)
                    candB[off + pos] = make_uint2((unsigned)d, r.y);
            }
            baseB += __popc(balB);
        }
        if (lane == 0) {
            s_cnt[wp][0][isB ? 1 : 0] = baseA;
            s_cnt[wp][1][isB ? 1 : 0] = baseB;
        }
    }
    __syncthreads();

    // ---- phase 2: consumer (one row per warp) ----
    {
        int r = isB ? 1 : 0;
        int b_eff = isB ? (b + 32) : b;
        float t0 = isB ? t0B : t0A;
        const float* myrow = isB ? s_waB : s_waA;
        uint2* cR = s_cand[wp][r];
        int n_lo = s_cnt[wp][r][0];
        int n_hi = s_cnt[wp][r][1];
        bool fb = (n_lo > RCAP) || (n_hi > RCAP);

        float sv[6];
#pragma unroll
        for (int k = 0; k < 6; k++) sv[k] = -3.0e38f;

        if (!fb) {
            int ntot = n_lo + n_hi;
            int kmax = (ntot + 31) >> 5;
#pragma unroll
            for (int k = 0; k < 6; k++) {
                if (k < kmax) {
                    int i = (k << 5) + lane;
                    if (i < ntot) {
                        int ph = (i < n_lo) ? i : (RCAP + i - n_lo);
                        uint2 cd = cR[ph];
                        float u = bits_to_u(cd.y);
                        sv[k] = myrow[cd.x] + 0.1f * nrm(u);
                    }
                }
            }
            int c0 = 0;
#pragma unroll
            for (int k = 0; k < 6; k++)
                c0 += __popc(__ballot_sync(0xffffffffu, sv[k] > t0));
            if (c0 < 32) fb = true;

            if (!fb) {
                float t = t0;
                if (c0 != 32) {
                    float til = t0, tih = 1.6f;
                    for (int it = 0; it < 32; it++) {
                        float tm = 0.5f * (til + tih);
                        int cc = 0;
#pragma unroll
                        for (int k = 0; k < 6; k++)
                            cc += __popc(__ballot_sync(0xffffffffu, sv[k] > tm));
                        if (cc >= 32) til = tm; else tih = tm;
                        if (cc == 32) break;
                    }
                    t = til;
                }
                unsigned bal[6];
#pragma unroll
                for (int k = 0; k < 6; k++)
                    bal[k] = __ballot_sync(0xffffffffu, sv[k] > t);
                int pre = 0;
#pragma unroll
                for (int k = 0; k < 6; k++) {
                    if (sv[k] > t) {
                        int rk = pre + __popc(bal[k] & below);
                        if (rk < KK) {
                            int i = (k << 5) + lane;
                            int ph = (i < n_lo) ? i : (RCAP + i - n_lo);
                            int d = (int)cR[ph].x;
                            atomicAdd(&g_s[b_eff * KK + rk],
                                      __float2uint_rn(myrow[d] * QSCALE));
                        }
                    }
                    pre += __popc(bal[k]);
                }
            }
        }
        if (fb) {
            // reuse this row's candidate slots as sort scratch
            float* fv = (float*)cR;                          // 64 floats
            unsigned short* fi = (unsigned short*)(cR + 96); // 64 u16, disjoint
            fallback_row(b_eff, rowbase, lane, isB, myrow, fv, fi);
        }
    }

    // ---- last-CTA epilogue: fold g_s -> bboxes, re-arm scratch ----
    __threadfence();
    __syncthreads();
    if (threadIdx.x == 0) {
        unsigned tk = atomicAdd(&g_ticket, 1u);
        s_last = (tk == NCTA - 1u);
    }
    __syncthreads();
    if (s_last) {
        __threadfence();
        for (int idx = threadIdx.x; idx < BB * KK; idx += 256) {
            unsigned acc = atomicExch(&g_s[idx], 0u);   // read + re-zero
            float sv = __uint2float_rn(acc) * (1.0f / (QSCALE * 920.0f));
            float r  = floorf(sv / 40.0f);
            float cc = sv - 40.0f * r;                  // jnp.mod(sv, 40)
            float x0 = (cc < 1.0f ? cc : cc - 1.0f) * 32.0f;
            float y0 = (r  < 1.0f ? r  : r  - 1.0f) * 32.0f;
            float x1 = (cc < 1.0f ? cc + 2.0f : cc + 1.0f) * 32.0f;
            float y1 = (r + 2.0f) * 32.0f;
            ((float4*)out)[idx] = make_float4(x0, y0, x1, y1);
        }
        if (threadIdx.x == 0) g_ticket = 0u;
    }
}

// ---------------------------------------------------------------------------
extern "C" void kernel_launch(void* const* d_in, const int* in_sizes, int n_in,
                              void* d_out, int out_size) {
    const float* wa = (const float*)d_in[2];   // weight_attn (64,23,40) -> (64,920)
    float* out = (float*)d_out;                // (64,32,4) float32

    prep_kernel<<<2, 1024>>>(wa);
    ftopk_kernel<<<dim3(NSMP / 4, BB / 2), 256>>>(wa, out);
}

// round 15
// speedup vs baseline: 1.2819x; 1.0426x over previous
#include <cuda_runtime.h>
#include <cstdint>

// Problem constants
#define BB   64
#define DD   920
#define NSMP 920
#define KK   32
#define TOT  (BB * NSMP * DD)   // 54,169,600
#define HALF (TOT / 2)          // 27,084,800
#define NCTA ((NSMP / 4) * (BB / 2))   // 7360 CTAs in the fused grid
#define RCAP 64                  // per-region candidate capacity

// Fixed-point accumulator for s[b,k]: sum of round(wa*2^22), <= 920*2^22 < 2^32.
// Zero-initialized at module load; the last-CTA epilogue restores it to zero
// after each consumption, so every launch / graph replay starts from 0.
__device__ unsigned g_s[BB * KK];     // 8 KB
__device__ unsigned g_ticket;         // last-CTA election; re-armed to 0
__device__ float    g_t0[BB];         // per-batch candidate threshold (prep)
__device__ unsigned g_B[BB * DD];     // bits-domain filter thresholds (prep)

#define QSCALE 4194304.0f             // 2^22

// ---------------------------------------------------------------------------
// threefry2x32 (JAX-exact), both outputs returned
// ---------------------------------------------------------------------------
__device__ __forceinline__ unsigned rotl32(unsigned x, int r) {
    return __funnelshift_l(x, x, r);
}

__device__ __forceinline__ uint2 threefry(unsigned c0, unsigned c1) {
    const unsigned ks0 = 0u, ks1 = 1u, ks2 = 0x1BD11BDAu ^ 0u ^ 1u;
    unsigned x0 = c0 + ks0;
    unsigned x1 = c1 + ks1;
#define RND(r) { x0 += x1; x1 = rotl32(x1, r); x1 ^= x0; }
    RND(13) RND(15) RND(26) RND(6)   x0 += ks1; x1 += ks2 + 1u;
    RND(17) RND(29) RND(16) RND(24)  x0 += ks2; x1 += ks0 + 2u;
    RND(13) RND(15) RND(26) RND(6)   x0 += ks0; x1 += ks1 + 3u;
    RND(17) RND(29) RND(16) RND(24)  x0 += ks1; x1 += ks2 + 4u;
    RND(13) RND(15) RND(26) RND(6)   x0 += ks2; x1 += ks0 + 5u;
#undef RND
    return make_uint2(x0, x1);
}

// bits -> u in [-1, 1): identical expression to all prior passing rounds.
__device__ __forceinline__ float bits_to_u(unsigned b) {
    const float LO = -0.99999994f;  // nextafterf(-1,0)
    float f = __uint_as_float((b >> 9) | 0x3f800000u) - 1.0f;
    return fmaxf(LO, f * 2.0f + LO);
}

// Rare (w >= 5, ~0.34% per value) tail: identical to prior rounds.
__device__ __noinline__ float erfinv_tail5(float u, float w) {
    w = sqrtf(w) - 3.0f;
    float p = -0.000200214257f;
    p = fmaf(p, w, 0.000100950558f);
    p = fmaf(p, w, 0.00134934322f);
    p = fmaf(p, w, -0.00367342844f);
    p = fmaf(p, w, 0.00573950773f);
    p = fmaf(p, w, -0.0076224613f);
    p = fmaf(p, w, 0.00943887047f);
    p = fmaf(p, w, 1.00167406f);
    p = fmaf(p, w, 2.83297682f);
    return 1.41421356f * (p * u);
}

// u -> sqrt(2)*erfinv(u), bit-identical to prior rounds' per-value math.
__device__ __forceinline__ float nrm(float u) {
    float x2 = u * u;
    float om = fmaf(x2, -1.0f, 1.0f);
    float w = -__logf(om);
    if (__builtin_expect(w < 5.0f, 1)) {
        w -= 2.5f;
        float p = 2.81022636e-08f;
        p = fmaf(p, w, 3.43273939e-07f);
        p = fmaf(p, w, -3.5233877e-06f);
        p = fmaf(p, w, -4.39150654e-06f);
        p = fmaf(p, w, 0.00021858087f);
        p = fmaf(p, w, -0.00125372503f);
        p = fmaf(p, w, -0.00417768164f);
        p = fmaf(p, w, 0.246640727f);
        p = fmaf(p, w, 1.50140941f);
        return (p * u) * 1.41421356f;
    }
    return erfinv_tail5(u, w);
}

// Exact-inverse bits-domain filter threshold (prep-time only).
// Prune u < ub  where  ub = erf((10*cw - 1e-3)/sqrt2):  any pruned value has
// nrm(u) <= 10*cw - 1e-3 + (poly+erff+bits errors << 1e-3)  =>  v < C < t0,
// so no possible top-32 winner is pruned (c0 >= 32 path; else fallback).
__device__ __forceinline__ unsigned mkB_exact(float wav, float C) {
    float cw = C - wav;
    if (cw <= 1e-4f) return 0u;                      // always pass
    float x = fmaf(10.0f, cw, -1e-3f) * 0.70710678f;
    float ub = fminf(erff(x), 0.999998f);            // cap: keep (M+1)<<9 < 2^32
    int M = (int)floorf((ub + 1.0f) * 4194304.0f) - 2;
    if (M < 0) return 0u;                            // always pass
    return ((unsigned)(M + 1)) << 9;
}

// ---------------------------------------------------------------------------
// Prep: one warp per b.  (1) bisect t0 with count(wa > t0) ~ 48-49;
// (2) fill the bits-threshold table g_B[b][*] using the exact erf inverse.
// ---------------------------------------------------------------------------
__global__ void __launch_bounds__(32) prep_kernel(const float* __restrict__ wa) {
    int gw = blockIdx.x;
    int lane = threadIdx.x;
    const float* row = wa + gw * DD;
    float v[29];
#pragma unroll
    for (int s = 0; s < 29; s++) {
        int d = s * 32 + lane;
        v[s] = (d < DD) ? row[d] : -1e30f;
    }
    float tl = 0.80f, th = 1.05f;
    for (int it = 0; it < 22; it++) {
        float t = 0.5f * (tl + th);
        int lc = 0;
#pragma unroll
        for (int s = 0; s < 29; s++) lc += (v[s] > t) ? 1 : 0;
        int c = __reduce_add_sync(0xffffffffu, lc);
        if (c > 48) tl = t; else th = t;
    }
    if (lane == 0) g_t0[gw] = tl;   // count(wa > tl) >= 49
    float C = tl - 1e-5f;
#pragma unroll
    for (int s = 0; s < 29; s++) {
        int d = s * 32 + lane;
        if (d < DD) g_B[gw * DD + d] = mkB_exact(v[s], C);
    }
}

// ---------------------------------------------------------------------------
// Fallback: full bit-identical row pipeline.  Taken when c0 < 32 or a
// candidate region overflows (rare).  Scratch = the row's candidate slots.
// ---------------------------------------------------------------------------
__device__ __noinline__ void fallback_row(int b_eff, unsigned rowbase, int lane,
                                          bool useHi, const float* myrow,
                                          float* s_val, unsigned short* s_idx) {
    float v[29];
#pragma unroll
    for (int s = 0; s < 29; s++) {
        int d = s * 32 + lane;
        if (d < DD) {
            unsigned i = rowbase + (unsigned)d;
            uint2 r = threefry(i, i + (unsigned)HALF);
            float u = bits_to_u(useHi ? r.y : r.x);
            v[s] = myrow[d] + 0.1f * nrm(u);
        } else v[s] = -3.0e38f;
    }

    float t = 1.0f;
    int c = 0;
    {
        float tl = 0.85f, th = 1.15f;
        for (int it = 0; it < 8; it++) {
            int lc = 0;
#pragma unroll
            for (int s = 0; s < 29; s++) lc += (v[s] > t) ? 1 : 0;
            c = __reduce_add_sync(0xffffffffu, lc);
            if (c >= 32 && c <= 64) break;
            if (c < 32) th = t; else tl = t;
            t = 0.5f * (tl + th);
        }
    }
    if (c < 32 || c > 64) {
        float tl = -8.0f, th = 8.0f;
        t = 0.0f;
        for (int it = 0; it < 60; it++) {
            int lc = 0;
#pragma unroll
            for (int s = 0; s < 29; s++) lc += (v[s] > t) ? 1 : 0;
            c = __reduce_add_sync(0xffffffffu, lc);
            if (c >= 32 && c <= 64) break;
            if (c < 32) th = t; else tl = t;
            t = 0.5f * (tl + th);
        }
    }

    int base = 0;
    unsigned below = (1u << lane) - 1u;
#pragma unroll
    for (int s = 0; s < 29; s++) {
        bool p = v[s] > t;
        unsigned bal = __ballot_sync(0xffffffffu, p);
        if (p) {
            int pos = base + __popc(bal & below);
            if (pos < 64) {
                s_val[pos] = v[s];
                s_idx[pos] = (unsigned short)(s * 32 + lane);
            }
        }
        base += __popc(bal);
    }
    __syncwarp();

    float s0 = (lane < c)      ? s_val[lane]      : -3.0e38f;
    float s1 = (lane + 32 < c) ? s_val[lane + 32] : -3.0e38f;

    if (c != 32) {
        float til = t, tih = 1.6f;
        for (int it = 0; it < 32; it++) {
            float tm = 0.5f * (til + tih);
            unsigned b0 = __ballot_sync(0xffffffffu, s0 > tm);
            unsigned b1 = __ballot_sync(0xffffffffu, s1 > tm);
            int cc = __popc(b0) + __popc(b1);
            if (cc >= 32) til = tm; else tih = tm;
            if (cc == 32) break;
        }
        t = til;
    }

    bool k0 = s0 > t, k1 = s1 > t;
    unsigned keep0 = __ballot_sync(0xffffffffu, k0);
    unsigned keep1 = __ballot_sync(0xffffffffu, k1);
    if (k0) {
        int r = __popc(keep0 & below);
        if (r < KK) {
            int d = (int)s_idx[lane];
            atomicAdd(&g_s[b_eff * KK + r], __float2uint_rn(myrow[d] * QSCALE));
        }
    }
    if (k1) {
        int r = __popc(keep0) + __popc(keep1 & below);
        if (r < KK) {
            int d = (int)s_idx[lane + 32];
            atomicAdd(&g_s[b_eff * KK + r], __float2uint_rn(myrow[d] * QSCALE));
        }
    }
}

// ---------------------------------------------------------------------------
// Fused kernel with exact-inverse bits-domain candidate pre-filtering.
// Phase 1: per value, ONE unsigned compare (bits >= B[d]) decides candidacy
// (~6.5% pass); passers store packed (d, bits) in ascending-d order.
// Phase 2: one row per warp; reconstruct u from bits (identical expression),
// dense erfinv on ~60 candidates (4 register rounds), exact-32 bisection,
// rank by position, fixed-point emit.
// Last CTA folds g_s -> bboxes and re-arms scratch.
// ---------------------------------------------------------------------------
__global__ void __launch_bounds__(256) ftopk_kernel(const float* __restrict__ wa,
                                                    float* __restrict__ out) {
    __shared__ float s_waA[DD];
    __shared__ float s_waB[DD];
    __shared__ unsigned s_BA[DD];                    // bits thresholds, row A
    __shared__ unsigned s_BB[DD];                    // bits thresholds, row B
    __shared__ uint2 s_cand[4][2][2 * RCAP];         // [pair][row][slot] (d, bits)
    __shared__ int s_cnt[4][2][2];                   // [pair][row][lo/hi]
    __shared__ bool s_last;

    int b = blockIdx.y;                 // 0..31 (pair: b and b+32)
    int warpid = threadIdx.x >> 5;
    int lane = threadIdx.x & 31;
    int wp = warpid & 3;
    bool isB = warpid >= 4;
    unsigned below = (1u << lane) - 1u;

    float t0A = g_t0[b];
    float t0B = g_t0[b + 32];
    for (int i = threadIdx.x; i < DD; i += 256) {
        s_waA[i] = wa[b * DD + i];
        s_waB[i] = wa[(b + 32) * DD + i];
        s_BA[i] = g_B[b * DD + i];
        s_BB[i] = g_B[(b + 32) * DD + i];
    }
    __syncthreads();

    int n = blockIdx.x * 4 + wp;        // gridDim.x = 230 -> n in [0,920)
    unsigned rowbase = (unsigned)((b * NSMP + n) * DD);  // < HALF (b < 32)

    // ---- phase 1: threefry + single-compare filter + compact (d,bits) ----
    {
        int sBeg = isB ? 15 : 0;
        int sEnd = isB ? 29 : 15;
        int off  = isB ? RCAP : 0;
        int baseA = 0, baseB = 0;
        uint2* candA = s_cand[wp][0];
        uint2* candB = s_cand[wp][1];
        for (int s = sBeg; s < sEnd; s++) {
            int d = s * 32 + lane;
            bool ok = d < DD;
            int dd = ok ? d : (DD - 1);
            unsigned i = rowbase + (unsigned)d;
            uint2 r = threefry(i, i + (unsigned)HALF);
            bool cA = ok && (r.x >= s_BA[dd]);
            bool cB = ok && (r.y >= s_BB[dd]);
            unsigned balA = __ballot_sync(0xffffffffu, cA);
            if (cA) {
                int pos = baseA + __popc(balA & below);
                if (pos < RCAP)
                    candA[off + pos] = make_uint2((unsigned)d, r.x);
            }
            baseA += __popc(balA);
            unsigned balB = __ballot_sync(0xffffffffu, cB);
            if (cB) {
                int pos = baseB + __popc(balB & below);
                if (pos < RCAP)
                    candB[off + pos] = make_uint2((unsigned)d, r.y);
            }
            baseB += __popc(balB);
        }
        if (lane == 0) {
            s_cnt[wp][0][isB ? 1 : 0] = baseA;
            s_cnt[wp][1][isB ? 1 : 0] = baseB;
        }
    }
    __syncthreads();

    // ---- phase 2: consumer (one row per warp) ----
    {
        int r = isB ? 1 : 0;
        int b_eff = isB ? (b + 32) : b;
        float t0 = isB ? t0B : t0A;
        const float* myrow = isB ? s_waB : s_waA;
        uint2* cR = s_cand[wp][r];
        int n_lo = s_cnt[wp][r][0];
        int n_hi = s_cnt[wp][r][1];
        bool fb = (n_lo > RCAP) || (n_hi > RCAP);

        float sv[4];
#pragma unroll
        for (int k = 0; k < 4; k++) sv[k] = -3.0e38f;

        if (!fb) {
            int ntot = n_lo + n_hi;     // <= 2*RCAP = 128
            int kmax = (ntot + 31) >> 5;
#pragma unroll
            for (int k = 0; k < 4; k++) {
                if (k < kmax) {
                    int i = (k << 5) + lane;
                    if (i < ntot) {
                        int ph = (i < n_lo) ? i : (RCAP + i - n_lo);
                        uint2 cd = cR[ph];
                        float u = bits_to_u(cd.y);
                        sv[k] = myrow[cd.x] + 0.1f * nrm(u);
                    }
                }
            }
            int c0 = 0;
#pragma unroll
            for (int k = 0; k < 4; k++)
                c0 += __popc(__ballot_sync(0xffffffffu, sv[k] > t0));
            if (c0 < 32) fb = true;

            if (!fb) {
                float t = t0;
                if (c0 != 32) {
                    float til = t0, tih = 1.6f;
                    for (int it = 0; it < 32; it++) {
                        float tm = 0.5f * (til + tih);
                        int cc = 0;
#pragma unroll
                        for (int k = 0; k < 4; k++)
                            cc += __popc(__ballot_sync(0xffffffffu, sv[k] > tm));
                        if (cc >= 32) til = tm; else tih = tm;
                        if (cc == 32) break;
                    }
                    t = til;
                }
                unsigned bal[4];
#pragma unroll
                for (int k = 0; k < 4; k++)
                    bal[k] = __ballot_sync(0xffffffffu, sv[k] > t);
                int pre = 0;
#pragma unroll
                for (int k = 0; k < 4; k++) {
                    if (sv[k] > t) {
                        int rk = pre + __popc(bal[k] & below);
                        if (rk < KK) {
                            int i = (k << 5) + lane;
                            int ph = (i < n_lo) ? i : (RCAP + i - n_lo);
                            int d = (int)cR[ph].x;
                            atomicAdd(&g_s[b_eff * KK + rk],
                                      __float2uint_rn(myrow[d] * QSCALE));
                        }
                    }
                    pre += __popc(bal[k]);
                }
            }
        }
        if (fb) {
            // reuse this row's candidate slots as sort scratch
            float* fv = (float*)cR;                          // 64 floats
            unsigned short* fi = (unsigned short*)(cR + 96); // 64 u16, disjoint
            fallback_row(b_eff, rowbase, lane, isB, myrow, fv, fi);
        }
    }

    // ---- last-CTA epilogue: fold g_s -> bboxes, re-arm scratch ----
    __threadfence();
    __syncthreads();
    if (threadIdx.x == 0) {
        unsigned tk = atomicAdd(&g_ticket, 1u);
        s_last = (tk == NCTA - 1u);
    }
    __syncthreads();
    if (s_last) {
        __threadfence();
        for (int idx = threadIdx.x; idx < BB * KK; idx += 256) {
            unsigned acc = atomicExch(&g_s[idx], 0u);   // read + re-zero
            float sv = __uint2float_rn(acc) * (1.0f / (QSCALE * 920.0f));
            float r  = floorf(sv / 40.0f);
            float cc = sv - 40.0f * r;                  // jnp.mod(sv, 40)
            float x0 = (cc < 1.0f ? cc : cc - 1.0f) * 32.0f;
            float y0 = (r  < 1.0f ? r  : r  - 1.0f) * 32.0f;
            float x1 = (cc < 1.0f ? cc + 2.0f : cc + 1.0f) * 32.0f;
            float y1 = (r + 2.0f) * 32.0f;
            ((float4*)out)[idx] = make_float4(x0, y0, x1, y1);
        }
        if (threadIdx.x == 0) g_ticket = 0u;
    }
}

// ---------------------------------------------------------------------------
extern "C" void kernel_launch(void* const* d_in, const int* in_sizes, int n_in,
                              void* d_out, int out_size) {
    const float* wa = (const float*)d_in[2];   // weight_attn (64,23,40) -> (64,920)
    float* out = (float*)d_out;                // (64,32,4) float32

    prep_kernel<<<BB, 32>>>(wa);
    ftopk_kernel<<<dim3(NSMP / 4, BB / 2), 256>>>(wa, out);
}

// round 16
// speedup vs baseline: 1.3917x; 1.0856x over previous
#include <cuda_runtime.h>
#include <cstdint>

// Problem constants
#define BB   64
#define DD   920
#define NSMP 920
#define KK   32
#define TOT  (BB * NSMP * DD)   // 54,169,600
#define HALF (TOT / 2)          // 27,084,800
#define NCTA ((NSMP / 4) * (BB / 2))   // 7360 CTAs in the fused grid
#define RCAP 64                  // per-region candidate capacity
#define DPAD 928                 // padded threshold-table width

// Fixed-point accumulator for s[b,k]: sum of round(wa*2^22), <= 920*2^22 < 2^32.
// Zero-initialized at module load; the last-CTA epilogue restores it to zero
// after each consumption, so every launch / graph replay starts from 0.
__device__ unsigned g_s[BB * KK];     // 8 KB
__device__ unsigned g_ticket;         // last-CTA election; re-armed to 0
__device__ float    g_t0[BB];         // per-batch candidate threshold (prep)
__device__ unsigned g_B[BB * DD];     // bits-domain filter thresholds (prep)

#define QSCALE 4194304.0f             // 2^22

// ---------------------------------------------------------------------------
// threefry2x32 (JAX-exact), both outputs returned
// ---------------------------------------------------------------------------
__device__ __forceinline__ unsigned rotl32(unsigned x, int r) {
    return __funnelshift_l(x, x, r);
}

__device__ __forceinline__ uint2 threefry(unsigned c0, unsigned c1) {
    const unsigned ks0 = 0u, ks1 = 1u, ks2 = 0x1BD11BDAu ^ 0u ^ 1u;
    unsigned x0 = c0 + ks0;
    unsigned x1 = c1 + ks1;
#define RND(r) { x0 += x1; x1 = rotl32(x1, r); x1 ^= x0; }
    RND(13) RND(15) RND(26) RND(6)   x0 += ks1; x1 += ks2 + 1u;
    RND(17) RND(29) RND(16) RND(24)  x0 += ks2; x1 += ks0 + 2u;
    RND(13) RND(15) RND(26) RND(6)   x0 += ks0; x1 += ks1 + 3u;
    RND(17) RND(29) RND(16) RND(24)  x0 += ks1; x1 += ks2 + 4u;
    RND(13) RND(15) RND(26) RND(6)   x0 += ks2; x1 += ks0 + 5u;
#undef RND
    return make_uint2(x0, x1);
}

// bits -> u in [-1, 1): identical expression to all prior passing rounds.
__device__ __forceinline__ float bits_to_u(unsigned b) {
    const float LO = -0.99999994f;  // nextafterf(-1,0)
    float f = __uint_as_float((b >> 9) | 0x3f800000u) - 1.0f;
    return fmaxf(LO, f * 2.0f + LO);
}

// Rare (w >= 5, ~0.34% per value) tail: identical to prior rounds.
__device__ __noinline__ float erfinv_tail5(float u, float w) {
    w = sqrtf(w) - 3.0f;
    float p = -0.000200214257f;
    p = fmaf(p, w, 0.000100950558f);
    p = fmaf(p, w, 0.00134934322f);
    p = fmaf(p, w, -0.00367342844f);
    p = fmaf(p, w, 0.00573950773f);
    p = fmaf(p, w, -0.0076224613f);
    p = fmaf(p, w, 0.00943887047f);
    p = fmaf(p, w, 1.00167406f);
    p = fmaf(p, w, 2.83297682f);
    return 1.41421356f * (p * u);
}

// u -> sqrt(2)*erfinv(u), bit-identical to prior rounds' per-value math.
__device__ __forceinline__ float nrm(float u) {
    float x2 = u * u;
    float om = fmaf(x2, -1.0f, 1.0f);
    float w = -__logf(om);
    if (__builtin_expect(w < 5.0f, 1)) {
        w -= 2.5f;
        float p = 2.81022636e-08f;
        p = fmaf(p, w, 3.43273939e-07f);
        p = fmaf(p, w, -3.5233877e-06f);
        p = fmaf(p, w, -4.39150654e-06f);
        p = fmaf(p, w, 0.00021858087f);
        p = fmaf(p, w, -0.00125372503f);
        p = fmaf(p, w, -0.00417768164f);
        p = fmaf(p, w, 0.246640727f);
        p = fmaf(p, w, 1.50140941f);
        return (p * u) * 1.41421356f;
    }
    return erfinv_tail5(u, w);
}

// Exact-inverse bits-domain filter threshold (prep-time only).
// Prune u < ub  where  ub = erf((10*cw - 1e-3)/sqrt2):  any pruned value has
// nrm(u) <= 10*cw - 1e-3 + (poly+erff+bits errors << 1e-3)  =>  v < C < t0,
// so no possible top-32 winner is pruned (c0 >= 32 path; else fallback).
__device__ __forceinline__ unsigned mkB_exact(float wav, float C) {
    float cw = C - wav;
    if (cw <= 1e-4f) return 0u;                      // always pass
    float x = fmaf(10.0f, cw, -1e-3f) * 0.70710678f;
    float ub = fminf(erff(x), 0.999998f);            // cap: keep (M+1)<<9 < 2^32
    int M = (int)floorf((ub + 1.0f) * 4194304.0f) - 2;
    if (M < 0) return 0u;                            // always pass
    return ((unsigned)(M + 1)) << 9;
}

// ---------------------------------------------------------------------------
// Prep: one CTA (256 thr) per b.  Warp 0 bisects t0 (count(wa > t0) ~ 48-49),
// then ALL 256 threads fill the bits-threshold row (4 erff each, not 29).
// ---------------------------------------------------------------------------
__global__ void __launch_bounds__(256) prep_kernel(const float* __restrict__ wa) {
    __shared__ float s_C;
    int gw = blockIdx.x;
    const float* row = wa + gw * DD;
    if (threadIdx.x < 32) {
        int lane = threadIdx.x;
        float v[29];
#pragma unroll
        for (int s = 0; s < 29; s++) {
            int d = s * 32 + lane;
            v[s] = (d < DD) ? row[d] : -1e30f;
        }
        float tl = 0.80f, th = 1.05f;
        for (int it = 0; it < 22; it++) {
            float t = 0.5f * (tl + th);
            int lc = 0;
#pragma unroll
            for (int s = 0; s < 29; s++) lc += (v[s] > t) ? 1 : 0;
            int c = __reduce_add_sync(0xffffffffu, lc);
            if (c > 48) tl = t; else th = t;
        }
        if (lane == 0) {
            g_t0[gw] = tl;          // count(wa > tl) >= 49
            s_C = tl - 1e-5f;
        }
    }
    __syncthreads();
    float C = s_C;
    for (int d = threadIdx.x; d < DD; d += 256)
        g_B[gw * DD + d] = mkB_exact(row[d], C);
}

// ---------------------------------------------------------------------------
// Fallback: full bit-identical row pipeline.  Taken when c0 < 32 or a
// candidate region overflows (rare).  Scratch = the row's candidate slots.
// ---------------------------------------------------------------------------
__device__ __noinline__ void fallback_row(int b_eff, unsigned rowbase, int lane,
                                          bool useHi, const float* myrow,
                                          float* s_val, unsigned short* s_idx) {
    float v[29];
#pragma unroll
    for (int s = 0; s < 29; s++) {
        int d = s * 32 + lane;
        if (d < DD) {
            unsigned i = rowbase + (unsigned)d;
            uint2 r = threefry(i, i + (unsigned)HALF);
            float u = bits_to_u(useHi ? r.y : r.x);
            v[s] = myrow[d] + 0.1f * nrm(u);
        } else v[s] = -3.0e38f;
    }

    float t = 1.0f;
    int c = 0;
    {
        float tl = 0.85f, th = 1.15f;
        for (int it = 0; it < 8; it++) {
            int lc = 0;
#pragma unroll
            for (int s = 0; s < 29; s++) lc += (v[s] > t) ? 1 : 0;
            c = __reduce_add_sync(0xffffffffu, lc);
            if (c >= 32 && c <= 64) break;
            if (c < 32) th = t; else tl = t;
            t = 0.5f * (tl + th);
        }
    }
    if (c < 32 || c > 64) {
        float tl = -8.0f, th = 8.0f;
        t = 0.0f;
        for (int it = 0; it < 60; it++) {
            int lc = 0;
#pragma unroll
            for (int s = 0; s < 29; s++) lc += (v[s] > t) ? 1 : 0;
            c = __reduce_add_sync(0xffffffffu, lc);
            if (c >= 32 && c <= 64) break;
            if (c < 32) th = t; else tl = t;
            t = 0.5f * (tl + th);
        }
    }

    int base = 0;
    unsigned below = (1u << lane) - 1u;
#pragma unroll
    for (int s = 0; s < 29; s++) {
        bool p = v[s] > t;
        unsigned bal = __ballot_sync(0xffffffffu, p);
        if (p) {
            int pos = base + __popc(bal & below);
            if (pos < 64) {
                s_val[pos] = v[s];
                s_idx[pos] = (unsigned short)(s * 32 + lane);
            }
        }
        base += __popc(bal);
    }
    __syncwarp();

    float s0 = (lane < c)      ? s_val[lane]      : -3.0e38f;
    float s1 = (lane + 32 < c) ? s_val[lane + 32] : -3.0e38f;

    if (c != 32) {
        float til = t, tih = 1.6f;
        for (int it = 0; it < 32; it++) {
            float tm = 0.5f * (til + tih);
            unsigned b0 = __ballot_sync(0xffffffffu, s0 > tm);
            unsigned b1 = __ballot_sync(0xffffffffu, s1 > tm);
            int cc = __popc(b0) + __popc(b1);
            if (cc >= 32) til = tm; else tih = tm;
            if (cc == 32) break;
        }
        t = til;
    }

    bool k0 = s0 > t, k1 = s1 > t;
    unsigned keep0 = __ballot_sync(0xffffffffu, k0);
    unsigned keep1 = __ballot_sync(0xffffffffu, k1);
    if (k0) {
        int r = __popc(keep0 & below);
        if (r < KK) {
            int d = (int)s_idx[lane];
            atomicAdd(&g_s[b_eff * KK + r], __float2uint_rn(myrow[d] * QSCALE));
        }
    }
    if (k1) {
        int r = __popc(keep0) + __popc(keep1 & below);
        if (r < KK) {
            int d = (int)s_idx[lane + 32];
            atomicAdd(&g_s[b_eff * KK + r], __float2uint_rn(myrow[d] * QSCALE));
        }
    }
}

// ---------------------------------------------------------------------------
// Fused kernel with exact-inverse bits-domain candidate pre-filtering.
// Phase 1 (fully unrolled, per-branch compile-time bounds): per value, ONE
// unsigned compare (bits >= B[d], one LDS.64 serves both rows) decides
// candidacy (~6.5% pass); passers store packed (d, bits) ascending-d.
// Phase 2: one row per warp; reconstruct u from bits (identical expression),
// dense erfinv on ~60 candidates (4 register rounds), exact-32 bisection,
// rank by position, fixed-point emit.
// Last CTA folds g_s -> bboxes and re-arms scratch.
// ---------------------------------------------------------------------------
__global__ void __launch_bounds__(256, 5) ftopk_kernel(const float* __restrict__ wa,
                                                       float* __restrict__ out) {
    __shared__ float s_waA[DD];
    __shared__ float s_waB[DD];
    __shared__ uint2 s_Bp[DPAD];                     // {B_rowA, B_rowB} per d
    __shared__ uint2 s_cand[4][2][2 * RCAP];         // [pair][row][slot] (d, bits)
    __shared__ int s_cnt[4][2][2];                   // [pair][row][lo/hi]
    __shared__ bool s_last;

    int b = blockIdx.y;                 // 0..31 (pair: b and b+32)
    int warpid = threadIdx.x >> 5;
    int lane = threadIdx.x & 31;
    int wp = warpid & 3;
    bool isB = warpid >= 4;
    unsigned below = (1u << lane) - 1u;

    float t0A = g_t0[b];
    float t0B = g_t0[b + 32];
    for (int i = threadIdx.x; i < DPAD; i += 256) {
        if (i < DD) {
            s_waA[i] = wa[b * DD + i];
            s_waB[i] = wa[(b + 32) * DD + i];
            s_Bp[i] = make_uint2(g_B[b * DD + i], g_B[(b + 32) * DD + i]);
        } else {
            s_Bp[i] = make_uint2(0xFFFFFFFFu, 0xFFFFFFFFu);  // pad: ~never pass
        }
    }
    __syncthreads();

    int n = blockIdx.x * 4 + wp;        // gridDim.x = 230 -> n in [0,920)
    unsigned rowbase = (unsigned)((b * NSMP + n) * DD);  // < HALF (b < 32)

    // ---- phase 1: threefry + single-compare filter + compact (d,bits) ----
    {
        int baseA = 0, baseB = 0;
        uint2* candA = s_cand[wp][0] + (isB ? RCAP : 0);
        uint2* candB = s_cand[wp][1] + (isB ? RCAP : 0);
        if (!isB) {
#pragma unroll
            for (int s = 0; s < 15; s++) {           // d <= 479 < DD: no checks
                int d = s * 32 + lane;
                unsigned i = rowbase + (unsigned)d;
                uint2 r = threefry(i, i + (unsigned)HALF);
                uint2 Bp = s_Bp[d];
                bool cA = r.x >= Bp.x;
                bool cB = r.y >= Bp.y;
                unsigned balA = __ballot_sync(0xffffffffu, cA);
                if (cA) {
                    int pos = baseA + __popc(balA & below);
                    if (pos < RCAP) candA[pos] = make_uint2((unsigned)d, r.x);
                }
                baseA += __popc(balA);
                unsigned balB = __ballot_sync(0xffffffffu, cB);
                if (cB) {
                    int pos = baseB + __popc(balB & below);
                    if (pos < RCAP) candB[pos] = make_uint2((unsigned)d, r.y);
                }
                baseB += __popc(balB);
            }
        } else {
#pragma unroll
            for (int s = 15; s < 29; s++) {          // only s==28 can overflow
                int d = s * 32 + lane;
                bool ok = (s < 28) || (lane < 24);   // compile-time except s=28
                unsigned i = rowbase + (unsigned)d;
                uint2 r = threefry(i, i + (unsigned)HALF);
                uint2 Bp = s_Bp[d];                  // padded table: safe load
                bool cA = ok && (r.x >= Bp.x);
                bool cB = ok && (r.y >= Bp.y);
                unsigned balA = __ballot_sync(0xffffffffu, cA);
                if (cA) {
                    int pos = baseA + __popc(balA & below);
                    if (pos < RCAP) candA[pos] = make_uint2((unsigned)d, r.x);
                }
                baseA += __popc(balA);
                unsigned balB = __ballot_sync(0xffffffffu, cB);
                if (cB) {
                    int pos = baseB + __popc(balB & below);
                    if (pos < RCAP) candB[pos] = make_uint2((unsigned)d, r.y);
                }
                baseB += __popc(balB);
            }
        }
        if (lane == 0) {
            s_cnt[wp][0][isB ? 1 : 0] = baseA;
            s_cnt[wp][1][isB ? 1 : 0] = baseB;
        }
    }
    __syncthreads();

    // ---- phase 2: consumer (one row per warp) ----
    {
        int r = isB ? 1 : 0;
        int b_eff = isB ? (b + 32) : b;
        float t0 = isB ? t0B : t0A;
        const float* myrow = isB ? s_waB : s_waA;
        uint2* cR = s_cand[wp][r];
        int n_lo = s_cnt[wp][r][0];
        int n_hi = s_cnt[wp][r][1];
        bool fb = (n_lo > RCAP) || (n_hi > RCAP);

        float sv[4];
#pragma unroll
        for (int k = 0; k < 4; k++) sv[k] = -3.0e38f;

        if (!fb) {
            int ntot = n_lo + n_hi;     // <= 2*RCAP = 128
            int kmax = (ntot + 31) >> 5;
#pragma unroll
            for (int k = 0; k < 4; k++) {
                if (k < kmax) {
                    int i = (k << 5) + lane;
                    if (i < ntot) {
                        int ph = (i < n_lo) ? i : (RCAP + i - n_lo);
                        uint2 cd = cR[ph];
                        float u = bits_to_u(cd.y);
                        sv[k] = myrow[cd.x] + 0.1f * nrm(u);
                    }
                }
            }
            int c0 = 0;
#pragma unroll
            for (int k = 0; k < 4; k++)
                c0 += __popc(__ballot_sync(0xffffffffu, sv[k] > t0));
            if (c0 < 32) fb = true;

            if (!fb) {
                float t = t0;
                if (c0 != 32) {
                    float til = t0, tih = 1.6f;
                    for (int it = 0; it < 32; it++) {
                        float tm = 0.5f * (til + tih);
                        int cc = 0;
#pragma unroll
                        for (int k = 0; k < 4; k++)
                            cc += __popc(__ballot_sync(0xffffffffu, sv[k] > tm));
                        if (cc >= 32) til = tm; else tih = tm;
                        if (cc == 32) break;
                    }
                    t = til;
                }
                unsigned bal[4];
#pragma unroll
                for (int k = 0; k < 4; k++)
                    bal[k] = __ballot_sync(0xffffffffu, sv[k] > t);
                int pre = 0;
#pragma unroll
                for (int k = 0; k < 4; k++) {
                    if (sv[k] > t) {
                        int rk = pre + __popc(bal[k] & below);
                        if (rk < KK) {
                            int i = (k << 5) + lane;
                            int ph = (i < n_lo) ? i : (RCAP + i - n_lo);
                            int d = (int)cR[ph].x;
                            atomicAdd(&g_s[b_eff * KK + rk],
                                      __float2uint_rn(myrow[d] * QSCALE));
                        }
                    }
                    pre += __popc(bal[k]);
                }
            }
        }
        if (fb) {
            // reuse this row's candidate slots as sort scratch
            float* fv = (float*)cR;                          // 64 floats
            unsigned short* fi = (unsigned short*)(cR + 96); // 64 u16, disjoint
            fallback_row(b_eff, rowbase, lane, isB, myrow, fv, fi);
        }
    }

    // ---- last-CTA epilogue: fold g_s -> bboxes, re-arm scratch ----
    __threadfence();
    __syncthreads();
    if (threadIdx.x == 0) {
        unsigned tk = atomicAdd(&g_ticket, 1u);
        s_last = (tk == NCTA - 1u);
    }
    __syncthreads();
    if (s_last) {
        __threadfence();
        for (int idx = threadIdx.x; idx < BB * KK; idx += 256) {
            unsigned acc = atomicExch(&g_s[idx], 0u);   // read + re-zero
            float sv = __uint2float_rn(acc) * (1.0f / (QSCALE * 920.0f));
            float r  = floorf(sv / 40.0f);
            float cc = sv - 40.0f * r;                  // jnp.mod(sv, 40)
            float x0 = (cc < 1.0f ? cc : cc - 1.0f) * 32.0f;
            float y0 = (r  < 1.0f ? r  : r  - 1.0f) * 32.0f;
            float x1 = (cc < 1.0f ? cc + 2.0f : cc + 1.0f) * 32.0f;
            float y1 = (r + 2.0f) * 32.0f;
            ((float4*)out)[idx] = make_float4(x0, y0, x1, y1);
        }
        if (threadIdx.x == 0) g_ticket = 0u;
    }
}

// ---------------------------------------------------------------------------
extern "C" void kernel_launch(void* const* d_in, const int* in_sizes, int n_in,
                              void* d_out, int out_size) {
    const float* wa = (const float*)d_in[2];   // weight_attn (64,23,40) -> (64,920)
    float* out = (float*)d_out;                // (64,32,4) float32

    prep_kernel<<<BB, 256>>>(wa);
    ftopk_kernel<<<dim3(NSMP / 4, BB / 2), 256>>>(wa, out);
}